// round 6
// baseline (speedup 1.0000x reference)
#include <cuda_runtime.h>

#define B_DIM 32
#define L_DIM 4096
#define D_DIM 768
#define D4 (D_DIM / 4)      // 192 float4 per position
#define P_PER_BLK 8
#define SLICES 4            // marker slices per row

// Scratch (no cudaMalloc allowed).
__device__ int g_sep[B_DIM];
__device__ int g_eos[B_DIM];
__device__ int g_psep[B_DIM * SLICES];
__device__ int g_peos[B_DIM * SLICES];

// Kernel 1a: each block scans one quarter-row for first token 4 (SEP) and
// first token 2 (EOS), writes partial mins. Handles int32 or int64 tokens:
// for int64 LE data every odd 32-bit word is 0 (tokens in [2, 32000]).
__global__ void find_markers_partial(const int* __restrict__ x32) {
    const int b     = blockIdx.x / SLICES;
    const int slice = blockIdx.x % SLICES;
    const int l_lo  = slice * (L_DIM / SLICES);

    const bool is64 = (x32[1] == 0) & (x32[3] == 0) & (x32[5] == 0) & (x32[7] == 0);

    int lsep = L_DIM, leos = L_DIM;
    if (!is64) {
        const int4* row = (const int4*)(x32 + (long long)b * L_DIM + l_lo);
        for (int k = threadIdx.x; k < (L_DIM / SLICES) / 4; k += blockDim.x) {
            const int4 v = row[k];
            const int base = l_lo + 4 * k;
            if (v.x == 4) lsep = min(lsep, base + 0);
            if (v.y == 4) lsep = min(lsep, base + 1);
            if (v.z == 4) lsep = min(lsep, base + 2);
            if (v.w == 4) lsep = min(lsep, base + 3);
            if (v.x == 2) leos = min(leos, base + 0);
            if (v.y == 2) leos = min(leos, base + 1);
            if (v.z == 2) leos = min(leos, base + 2);
            if (v.w == 2) leos = min(leos, base + 3);
        }
    } else {
        const int4* row = (const int4*)(x32 + ((long long)b * L_DIM + l_lo) * 2);
        for (int k = threadIdx.x; k < (L_DIM / SLICES) / 2; k += blockDim.x) {
            const int4 v = row[k];
            const int base = l_lo + 2 * k;
            if (v.x == 4) lsep = min(lsep, base + 0);
            if (v.z == 4) lsep = min(lsep, base + 1);
            if (v.x == 2) leos = min(leos, base + 0);
            if (v.z == 2) leos = min(leos, base + 1);
        }
    }
    #pragma unroll
    for (int off = 16; off > 0; off >>= 1) {
        lsep = min(lsep, __shfl_down_sync(0xFFFFFFFFu, lsep, off));
        leos = min(leos, __shfl_down_sync(0xFFFFFFFFu, leos, off));
    }
    __shared__ int s_sep[8], s_eos[8];
    const int wid = threadIdx.x >> 5;
    if ((threadIdx.x & 31) == 0) { s_sep[wid] = lsep; s_eos[wid] = leos; }
    __syncthreads();
    if (threadIdx.x == 0) {
        int ms = s_sep[0], me = s_eos[0];
        for (int w = 1; w < (int)(blockDim.x >> 5); w++) {
            ms = min(ms, s_sep[w]);
            me = min(me, s_eos[w]);
        }
        g_psep[blockIdx.x] = ms;
        g_peos[blockIdx.x] = me;
    }
}

// Kernel 1b: reduce slice partials. One warp, b = lane.
__global__ void reduce_markers() {
    const int b = threadIdx.x;
    if (b < B_DIM) {
        int ms = L_DIM, me = L_DIM;
        #pragma unroll
        for (int s = 0; s < SLICES; s++) {
            ms = min(ms, g_psep[b * SLICES + s]);
            me = min(me, g_peos[b * SLICES + s]);
        }
        g_sep[b] = ms;
        g_eos[b] = me;
    }
}

// Kernel 2: 192 threads = one D-row; each block writes 8 consecutive positions.
// Segments form runs 1..1,2..2,0..0 with pairwise-distinct values, so
// seg(first)==seg(last) <=> whole block uniform -> 1 LDG + 8 STG per thread.
__global__ void __launch_bounds__(192) write_embedding_kernel(
    const float4* __restrict__ W4, float4* __restrict__ out) {
    const int tid = threadIdx.x;
    const int p0  = blockIdx.x * P_PER_BLK;
    const int b   = p0 >> 12;           // / L_DIM (blocks never straddle rows)
    const int l0  = p0 & (L_DIM - 1);

    const int sep = g_sep[b];
    const int eos = g_eos[b];
    const int seg0 = (l0 < sep) ? 1 : ((l0 < eos) ? 2 : 0);
    const int lN   = l0 + P_PER_BLK - 1;
    const int segN = (lN < sep) ? 1 : ((lN < eos) ? 2 : 0);

    float4* __restrict__ o = out + (long long)p0 * D4 + tid;

    if (seg0 == segN) {                  // uniform block (>=99.4% of blocks)
        const float4 v = __ldg(W4 + seg0 * D4 + tid);
        #pragma unroll
        for (int j = 0; j < P_PER_BLK; j++)
            o[j * D4] = v;
    } else {                             // boundary block (rare)
        #pragma unroll
        for (int j = 0; j < P_PER_BLK; j++) {
            const int l = l0 + j;
            const int seg = (l < sep) ? 1 : ((l < eos) ? 2 : 0);
            o[j * D4] = __ldg(W4 + seg * D4 + tid);
        }
    }
}

extern "C" void kernel_launch(void* const* d_in, const int* in_sizes, int n_in,
                              void* d_out, int out_size) {
    // Identify inputs by element count: x has B*L, W has 3*D.
    const int* x;
    const float* W;
    if (in_sizes[0] == B_DIM * L_DIM) {
        x = (const int*)d_in[0];
        W = (const float*)d_in[1];
    } else {
        x = (const int*)d_in[1];
        W = (const float*)d_in[0];
    }

    find_markers_partial<<<B_DIM * SLICES, 256>>>(x);
    reduce_markers<<<1, 32>>>();

    // B*L / P_PER_BLK = 131072 / 8 = 16384 blocks
    write_embedding_kernel<<<(B_DIM * L_DIM) / P_PER_BLK, 192>>>(
        (const float4*)W, (float4*)d_out);
}

// round 8
// speedup vs baseline: 1.0252x; 1.0252x over previous
#include <cuda_runtime.h>

#define B_DIM 32
#define L_DIM 4096
#define D_DIM 768
#define D4 (D_DIM / 4)      // 192 float4 per position
#define P_PER_BLK 8
#define SLICES 8            // marker slices per row

// Scratch (no cudaMalloc allowed).
__device__ int g_psep[B_DIM * SLICES];
__device__ int g_peos[B_DIM * SLICES];

// Kernel 1: 256 blocks, each scans one 512-token slice for first token 4 (SEP)
// and first token 2 (EOS); writes partial mins. Handles int32 or int64 tokens:
// for int64 LE data every odd 32-bit word is 0 (tokens in [2, 32000]).
__global__ void __launch_bounds__(128) find_markers_partial(const int* __restrict__ x32) {
    const int b     = blockIdx.x >> 3;        // / SLICES
    const int slice = blockIdx.x & (SLICES - 1);
    const int l_lo  = slice * (L_DIM / SLICES);

    const bool is64 = (x32[1] == 0) & (x32[3] == 0) & (x32[5] == 0) & (x32[7] == 0);

    int lsep = L_DIM, leos = L_DIM;
    if (!is64) {
        // 512 tokens = 128 int4 -> exactly one load per thread
        const int4* row = (const int4*)(x32 + (long long)b * L_DIM + l_lo);
        const int k = threadIdx.x;
        const int4 v = row[k];
        const int base = l_lo + 4 * k;
        if (v.x == 4) lsep = min(lsep, base + 0);
        if (v.y == 4) lsep = min(lsep, base + 1);
        if (v.z == 4) lsep = min(lsep, base + 2);
        if (v.w == 4) lsep = min(lsep, base + 3);
        if (v.x == 2) leos = min(leos, base + 0);
        if (v.y == 2) leos = min(leos, base + 1);
        if (v.z == 2) leos = min(leos, base + 2);
        if (v.w == 2) leos = min(leos, base + 3);
    } else {
        // 512 tokens = 256 int4 -> two loads per thread
        const int4* row = (const int4*)(x32 + ((long long)b * L_DIM + l_lo) * 2);
        #pragma unroll
        for (int it = 0; it < 2; it++) {
            const int k = threadIdx.x + it * 128;
            const int4 v = row[k];
            const int base = l_lo + 2 * k;
            if (v.x == 4) lsep = min(lsep, base + 0);
            if (v.z == 4) lsep = min(lsep, base + 1);
            if (v.x == 2) leos = min(leos, base + 0);
            if (v.z == 2) leos = min(leos, base + 1);
        }
    }
    #pragma unroll
    for (int off = 16; off > 0; off >>= 1) {
        lsep = min(lsep, __shfl_down_sync(0xFFFFFFFFu, lsep, off));
        leos = min(leos, __shfl_down_sync(0xFFFFFFFFu, leos, off));
    }
    __shared__ int s_sep[4], s_eos[4];
    const int wid = threadIdx.x >> 5;
    if ((threadIdx.x & 31) == 0) { s_sep[wid] = lsep; s_eos[wid] = leos; }
    __syncthreads();
    if (threadIdx.x == 0) {
        int ms = min(min(s_sep[0], s_sep[1]), min(s_sep[2], s_sep[3]));
        int me = min(min(s_eos[0], s_eos[1]), min(s_eos[2], s_eos[3]));
        g_psep[blockIdx.x] = ms;
        g_peos[blockIdx.x] = me;
    }
}

// Kernel 2: 192 threads = one D-row; each block writes 8 consecutive positions.
// Thread 0 reduces the row's slice partials (L2-hit) and broadcasts via smem.
// Segments form runs 1..1,2..2,0..0 with pairwise-distinct values, so
// seg(first)==seg(last) <=> whole block uniform -> 1 LDG + 8 STG per thread.
__global__ void __launch_bounds__(192) write_embedding_kernel(
    const float4* __restrict__ W4, float4* __restrict__ out) {
    const int tid = threadIdx.x;
    const int p0  = blockIdx.x * P_PER_BLK;
    const int b   = p0 >> 12;           // / L_DIM (blocks never straddle rows)
    const int l0  = p0 & (L_DIM - 1);

    __shared__ int sh_sep, sh_eos;
    if (tid == 0) {
        int ms = L_DIM, me = L_DIM;
        #pragma unroll
        for (int s = 0; s < SLICES; s++) {
            ms = min(ms, g_psep[b * SLICES + s]);
            me = min(me, g_peos[b * SLICES + s]);
        }
        sh_sep = ms;
        sh_eos = me;
    }
    __syncthreads();
    const int sep = sh_sep;
    const int eos = sh_eos;

    const int seg0 = (l0 < sep) ? 1 : ((l0 < eos) ? 2 : 0);
    const int lN   = l0 + P_PER_BLK - 1;
    const int segN = (lN < sep) ? 1 : ((lN < eos) ? 2 : 0);

    float4* __restrict__ o = out + (long long)p0 * D4 + tid;

    if (seg0 == segN) {                  // uniform block (>=99.4% of blocks)
        const float4 v = __ldg(W4 + seg0 * D4 + tid);
        #pragma unroll
        for (int j = 0; j < P_PER_BLK; j++)
            o[j * D4] = v;
    } else {                             // boundary block (rare)
        #pragma unroll
        for (int j = 0; j < P_PER_BLK; j++) {
            const int l = l0 + j;
            const int seg = (l < sep) ? 1 : ((l < eos) ? 2 : 0);
            o[j * D4] = __ldg(W4 + seg * D4 + tid);
        }
    }
}

extern "C" void kernel_launch(void* const* d_in, const int* in_sizes, int n_in,
                              void* d_out, int out_size) {
    // Identify inputs by element count: x has B*L, W has 3*D.
    const int* x;
    const float* W;
    if (in_sizes[0] == B_DIM * L_DIM) {
        x = (const int*)d_in[0];
        W = (const float*)d_in[1];
    } else {
        x = (const int*)d_in[1];
        W = (const float*)d_in[0];
    }

    find_markers_partial<<<B_DIM * SLICES, 128>>>(x);

    // B*L / P_PER_BLK = 131072 / 8 = 16384 blocks
    write_embedding_kernel<<<(B_DIM * L_DIM) / P_PER_BLK, 192>>>(
        (const float4*)W, (float4*)d_out);
}